// round 6
// baseline (speedup 1.0000x reference)
#include <cuda_runtime.h>
#include <cuda_fp16.h>
#include <cstdint>

// ===================== problem constants =====================
#define BB    16384
#define INSZ  4096
#define PP    8
#define DD    512
#define BM    128
#define BN    128
#define BK    64
#define NKT   8          // 512/64

// ===================== scratch (module-load allocated) =====================
__device__ __align__(256) __half g_Xh [(size_t)BB * INSZ];    // x*gain1+nbias1, fp16
__device__ __align__(256) __half g_O1h[(size_t)BB * INSZ];    // layer-1 activation, fp16
__device__ __align__(256) __half g_W1T[(size_t)PP * DD * DD]; // W1^T: [p][e][d]
__device__ __align__(256) __half g_W2T[(size_t)PP * DD * DD]; // W2^T: [p][e][d]

// ===================== helpers =====================
__device__ __forceinline__ uint32_t smem_u32(const void* p) {
    uint32_t a;
    asm("{ .reg .u64 t; cvta.to.shared.u64 t, %1; cvt.u32.u64 %0, t; }" : "=r"(a) : "l"(p));
    return a;
}

#define SW128(o) ((o) ^ (((o) >> 3) & 0x70))

#define CP_ASYNC16(saddr, gptr) \
    asm volatile("cp.async.cg.shared.global [%0], [%1], 16;" :: "r"(saddr), "l"(gptr))
#define CP_COMMIT() asm volatile("cp.async.commit_group;")
#define CP_WAIT1()  asm volatile("cp.async.wait_group 1;" ::: "memory")
#define CP_WAIT0()  asm volatile("cp.async.wait_group 0;" ::: "memory")

#define LDSM4(r0, r1, r2, r3, addr) \
    asm volatile("ldmatrix.sync.aligned.m8n8.x4.shared.b16 {%0,%1,%2,%3}, [%4];" \
        : "=r"(r0), "=r"(r1), "=r"(r2), "=r"(r3) : "r"(addr))

__device__ __forceinline__ void mma16816(float* c, const uint32_t* a, const uint32_t* b) {
    asm volatile(
        "mma.sync.aligned.m16n8k16.row.col.f32.f16.f16.f32 "
        "{%0,%1,%2,%3}, {%4,%5,%6,%7}, {%8,%9}, {%0,%1,%2,%3};"
        : "+f"(c[0]), "+f"(c[1]), "+f"(c[2]), "+f"(c[3])
        : "r"(a[0]), "r"(a[1]), "r"(a[2]), "r"(a[3]), "r"(b[0]), "r"(b[1]));
}

// ===================== smem layout =====================
// [0 .. 1536)    : 3 x 128 f32 epilogue params (bias, gamma, beta)
// [2048 ..)      : 3 stages x (A 16KB + B 16KB)
#define SM_PAR    0
#define SM_STAGE  2048
#define STAGE_STRIDE 32768
#define STAGE_B_OFF  16384
#define SMEM_GEMM (SM_STAGE + 3 * STAGE_STRIDE)   // 100352 B

// ===================== pre-convert kernels =====================
__global__ void convert_x_kernel(const float* __restrict__ x,
                                 const float* __restrict__ gain1,
                                 const float* __restrict__ nbias1) {
    float g = gain1[0], nb = nbias1[0];
    size_t i = (size_t)blockIdx.x * blockDim.x + threadIdx.x;   // over float4s
    float4 v = ((const float4*)x)[i];
    __half2 a = __floats2half2_rn(v.x * g + nb, v.y * g + nb);
    __half2 b = __floats2half2_rn(v.z * g + nb, v.w * g + nb);
    uint2 w;
    w.x = *reinterpret_cast<uint32_t*>(&a);
    w.y = *reinterpret_cast<uint32_t*>(&b);
    ((uint2*)g_Xh)[i] = w;
}

__global__ void convert_w_kernel(const float* __restrict__ w1,
                                 const float* __restrict__ w2) {
    __shared__ float tile[32][33];
    int z = blockIdx.z;                      // 0..15: layer*8 + p
    const float* src = (z < 8 ? w1 : w2) + (size_t)(z & 7) * DD * DD;
    __half* dst = (z < 8 ? g_W1T : g_W2T) + (size_t)(z & 7) * DD * DD;
    int d0 = blockIdx.y * 32, e0 = blockIdx.x * 32;
    tile[threadIdx.y][threadIdx.x] = src[(size_t)(d0 + threadIdx.y) * DD + e0 + threadIdx.x];
    __syncthreads();
    dst[(size_t)(e0 + threadIdx.y) * DD + d0 + threadIdx.x] =
        __float2half(tile[threadIdx.x][threadIdx.y]);
}

// ===================== fused GEMM kernels (legacy HMMA path) =====================
// LAYER==0: o1h = f16( swish1(Xh @ W1T^T + b1) * gain3 + nbias3 )
// LAYER==1: out = swish3(o1h @ W2T^T + b2) + x
template <int LAYER>
__global__ void __launch_bounds__(256, 2)
gemm_kernel(const float* __restrict__ xres,
            const float* __restrict__ bias,
            const float* __restrict__ gamma, const float* __restrict__ beta,
            const float* __restrict__ gainp, const float* __restrict__ nbiasp,
            float* __restrict__ out) {
    extern __shared__ char smem[];
    const uint32_t smem_base = smem_u32(smem);
    const int tid = threadIdx.x, lane = tid & 31, wid = tid >> 5;
    const int wm = wid & 1, wn = wid >> 1;          // warp grid 2(M) x 4(N)
    const int p = blockIdx.z;
    const int n0 = blockIdx.y * BN;                  // col offset within partition
    const int row0 = blockIdx.x * BM;

    // epilogue params for this CTA's 128 columns
    float* bs = (float*)(smem + SM_PAR);
    float* gs = bs + 128;
    float* es = gs + 128;
    if (tid < 128) {
        int gc = p * DD + n0 + tid;
        bs[tid] = __ldg(bias + gc);
        gs[tid] = __ldg(gamma + gc);
        es[tid] = __ldg(beta + gc);
    }
    float gain = 1.0f, nbias = 0.0f;
    if (LAYER == 0) { gain = __ldg(gainp); nbias = __ldg(nbiasp); }

    const __half* __restrict__ Ag =
        (LAYER == 0 ? g_Xh : g_O1h) + (size_t)row0 * INSZ + p * DD;
    const __half* __restrict__ Bg =
        (LAYER == 0 ? g_W1T : g_W2T) + (size_t)p * DD * DD + (size_t)n0 * DD;

    // ---- cp.async tile loaders: 128 rows x 64 halves (128B rows), SW128 ----
    auto load_stage = [&](int s, int kt) {
        uint32_t sa = smem_base + SM_STAGE + s * STAGE_STRIDE;
        const __half* ga = Ag + kt * BK;
        #pragma unroll
        for (int i = 0; i < 4; i++) {               // 128 rows * 8 segs / 256 thr
            int idx = i * 256 + tid; int r = idx >> 3, seg = idx & 7;
            CP_ASYNC16(sa + SW128(r * 128 + seg * 16), ga + (size_t)r * INSZ + seg * 8);
        }
        uint32_t sb = sa + STAGE_B_OFF;
        const __half* gb = Bg + kt * BK;
        #pragma unroll
        for (int i = 0; i < 4; i++) {
            int idx = i * 256 + tid; int r = idx >> 3, seg = idx & 7;
            CP_ASYNC16(sb + SW128(r * 128 + seg * 16), gb + (size_t)r * DD + seg * 8);
        }
        CP_COMMIT();
    };

    float acc[4][4][4];
    #pragma unroll
    for (int mi = 0; mi < 4; mi++)
        #pragma unroll
        for (int ni = 0; ni < 4; ni++)
            #pragma unroll
            for (int e = 0; e < 4; e++) acc[mi][ni][e] = 0.0f;

    // ---- 3-stage pipeline ----
    load_stage(0, 0);
    load_stage(1, 1);
    for (int kt = 0; kt < NKT; kt++) {
        if (kt == NKT - 1) CP_WAIT0(); else CP_WAIT1();
        __syncthreads();
        if (kt + 2 < NKT) load_stage((kt + 2) % 3, kt + 2);

        uint32_t sA = smem_base + SM_STAGE + (kt % 3) * STAGE_STRIDE;
        uint32_t sB = sA + STAGE_B_OFF;
        #pragma unroll
        for (int ks = 0; ks < 4; ks++) {
            uint32_t a[4][4];
            #pragma unroll
            for (int mi = 0; mi < 4; mi++) {
                int r = wm * 64 + mi * 16 + (lane & 15);
                int c = ks * 16 + (lane >> 4) * 8;
                uint32_t addr = sA + SW128(r * 128 + c * 2);
                LDSM4(a[mi][0], a[mi][1], a[mi][2], a[mi][3], addr);
            }
            uint32_t b[4][2];
            #pragma unroll
            for (int nj = 0; nj < 2; nj++) {
                int r = wn * 32 + nj * 16 + (lane & 7) + ((lane >> 4) * 8);
                int c = ks * 16 + ((lane >> 3) & 1) * 8;
                uint32_t addr = sB + SW128(r * 128 + c * 2);
                LDSM4(b[2 * nj][0], b[2 * nj][1], b[2 * nj + 1][0], b[2 * nj + 1][1], addr);
            }
            #pragma unroll
            for (int mi = 0; mi < 4; mi++)
                #pragma unroll
                for (int ni = 0; ni < 4; ni++)
                    mma16816(acc[mi][ni], a[mi], b[ni]);
        }
    }
    __syncthreads();

    // ---- epilogue ----
    #pragma unroll
    for (int mi = 0; mi < 4; mi++) {
        #pragma unroll
        for (int ni = 0; ni < 4; ni++) {
            int rloc = wm * 64 + mi * 16 + (lane >> 2);
            int cloc = wn * 32 + ni * 8 + ((lane & 3) << 1);
            float b0 = bs[cloc], b1v = bs[cloc + 1];
            float g0 = gs[cloc], g1v = gs[cloc + 1];
            float e0 = es[cloc], e1v = es[cloc + 1];
            size_t base0 = (size_t)(row0 + rloc) * INSZ + p * DD + n0 + cloc;
            size_t base1 = base0 + 8 * INSZ;
            float* c = acc[mi][ni];
            float y00 = c[0] + b0, y01 = c[1] + b1v;
            float y10 = c[2] + b0, y11 = c[3] + b1v;
            float s00 = 1.0f / (1.0f + __expf(-e0 * y00));
            float s01 = 1.0f / (1.0f + __expf(-e1v * y01));
            float s10 = 1.0f / (1.0f + __expf(-e0 * y10));
            float s11 = 1.0f / (1.0f + __expf(-e1v * y11));
            float o00 = (g0 + s00 * (1.0f - g0)) * y00;
            float o01 = (g1v + s01 * (1.0f - g1v)) * y01;
            float o10 = (g0 + s10 * (1.0f - g0)) * y10;
            float o11 = (g1v + s11 * (1.0f - g1v)) * y11;
            if (LAYER == 0) {
                __half2 h0 = __floats2half2_rn(o00 * gain + nbias, o01 * gain + nbias);
                __half2 h1 = __floats2half2_rn(o10 * gain + nbias, o11 * gain + nbias);
                *(__half2*)(g_O1h + base0) = h0;
                *(__half2*)(g_O1h + base1) = h1;
            } else {
                float2 x0 = *(const float2*)(xres + base0);
                float2 x1 = *(const float2*)(xres + base1);
                float2 r0 = make_float2(o00 + x0.x, o01 + x0.y);
                float2 r1 = make_float2(o10 + x1.x, o11 + x1.y);
                *(float2*)(out + base0) = r0;
                *(float2*)(out + base1) = r1;
            }
        }
    }
}

// ===================== launch =====================
extern "C" void kernel_launch(void* const* d_in, const int* in_sizes, int n_in,
                              void* d_out, int out_size) {
    (void)in_sizes; (void)n_in; (void)out_size;
    const float* x      = (const float*)d_in[0];
    const float* w1     = (const float*)d_in[1];
    const float* bias1  = (const float*)d_in[2];
    const float* w2     = (const float*)d_in[3];
    const float* bias2  = (const float*)d_in[4];
    const float* gamma1 = (const float*)d_in[5];
    const float* beta1  = (const float*)d_in[6];
    const float* gamma3 = (const float*)d_in[7];
    const float* beta3  = (const float*)d_in[8];
    const float* gain1  = (const float*)d_in[9];
    const float* nbias1 = (const float*)d_in[10];
    const float* gain3  = (const float*)d_in[11];
    const float* nbias3 = (const float*)d_in[12];
    float* out = (float*)d_out;

    cudaFuncSetAttribute(gemm_kernel<0>,
                         cudaFuncAttributeMaxDynamicSharedMemorySize, SMEM_GEMM);
    cudaFuncSetAttribute(gemm_kernel<1>,
                         cudaFuncAttributeMaxDynamicSharedMemorySize, SMEM_GEMM);

    // x -> fp16 with gain1/nbias1 folded
    convert_x_kernel<<<(BB * (size_t)INSZ / 4) / 256, 256>>>(x, gain1, nbias1);
    // W1/W2 -> fp16, transposed to [p][e][d] (K-contiguous B operand)
    convert_w_kernel<<<dim3(16, 16, 16), dim3(32, 32)>>>(w1, w2);

    dim3 grid(BB / BM, DD / BN, PP);   // (128, 4, 8)
    gemm_kernel<0><<<grid, 256, SMEM_GEMM>>>(nullptr, bias1, gamma1, beta1,
                                             gain3, nbias3, nullptr);
    gemm_kernel<1><<<grid, 256, SMEM_GEMM>>>(x, bias2, gamma3, beta3,
                                             nullptr, nullptr, out);
}